// round 5
// baseline (speedup 1.0000x reference)
#include <cuda_runtime.h>
#include <math.h>

#define NIN 14
#define NH 256
#define KTOT 10
#define TM 64
#define NTHREADS 256
#define XROW 272   // 256 summary + 14 tower + 2 zero pad

typedef unsigned long long u64t;

// fma.rn.f32x2: d.lo = a.lo*b.lo + d.lo ; d.hi = a.hi*b.hi + d.hi  (sm_100+)
#define FMA_F32X2(d, a, b) \
    asm("fma.rn.f32x2 %0, %1, %2, %0;" : "+l"(d) : "l"(a), "l"(b))

// ---------------------------------------------------------------------------
// Repacked weights: k-pair interleaved so the packed-f32x2 GEMM can load
// 64-bit {W[2kp][j], W[2kp+1][j]} pairs directly.
// Layout: Wp[kp*512 + j*2 + {0,1}]  (512 floats per kp block, 256 cols)
// First-layer weights padded from 270 -> 272 rows (rows 270,271 zero).
// ---------------------------------------------------------------------------
__device__ __align__(16) float g_M1wp[(XROW / 2) * NH * 2];   // 136 kp
__device__ __align__(16) float g_O1wp[(XROW / 2) * NH * 2];
__device__ __align__(16) float g_M2wp[(NH / 2) * NH * 2];     // 128 kp
__device__ __align__(16) float g_M3wp[(NH / 2) * NH * 2];
__device__ __align__(16) float g_O2wp[(NH / 2) * NH * 2];

__global__ void repack_weights_kernel(const float* __restrict__ M1w,
                                      const float* __restrict__ O1w,
                                      const float* __restrict__ M2w,
                                      const float* __restrict__ M3w,
                                      const float* __restrict__ O2w) {
    int idx = blockIdx.x * blockDim.x + threadIdx.x;   // over 136*256
    if (idx >= (XROW / 2) * NH) return;
    int kp = idx >> 8;
    int j  = idx & 255;
    int k0 = 2 * kp, k1 = 2 * kp + 1;

    // first layers: 270 real rows
    float m0 = (k0 < 270) ? M1w[k0 * NH + j] : 0.f;
    float m1 = (k1 < 270) ? M1w[k1 * NH + j] : 0.f;
    float o0 = (k0 < 270) ? O1w[k0 * NH + j] : 0.f;
    float o1 = (k1 < 270) ? O1w[k1 * NH + j] : 0.f;
    g_M1wp[idx * 2]     = m0;
    g_M1wp[idx * 2 + 1] = m1;
    g_O1wp[idx * 2]     = o0;
    g_O1wp[idx * 2 + 1] = o1;

    if (kp < NH / 2) {
        g_M2wp[idx * 2]     = M2w[k0 * NH + j];
        g_M2wp[idx * 2 + 1] = M2w[k1 * NH + j];
        g_M3wp[idx * 2]     = M3w[k0 * NH + j];
        g_M3wp[idx * 2 + 1] = M3w[k1 * NH + j];
        g_O2wp[idx * 2]     = O2w[k0 * NH + j];
        g_O2wp[idx * 2 + 1] = O2w[k1 * NH + j];
    }
}

// ---------------------------------------------------------------------------
// Packed-f32x2 GEMM: Out[64][256] = relu(In[64][KD] @ W[KD][256] + bias)
// Warp grid 2x4 (32 rows x 64 cols per warp); lane grid 4x8 (8x8 per thread).
// Accumulators pair the K dimension: acc.lo = even-k partial, acc.hi = odd-k.
// A pairs come straight from LDS.128; B pairs from the repacked weights.
// ---------------------------------------------------------------------------
template <int KD>
__device__ __forceinline__ void gemm_relu_256(
    const float* __restrict__ In, const int inRow,
    const float* __restrict__ Wp, const float* __restrict__ bias,
    float* __restrict__ Out, const int outRow, const int tid)
{
    const int wid  = tid >> 5;
    const int lane = tid & 31;
    const int lr   = lane >> 3;      // 0..3
    const int lc   = lane & 7;       // 0..7
    const int rBase = (wid >> 2) * 32 + lr * 8;
    const int cBase = (wid & 3) * 64 + lc * 8;

    u64t acc[8][8];
#pragma unroll
    for (int i = 0; i < 8; i++)
#pragma unroll
        for (int j = 0; j < 8; j++) acc[i][j] = 0ull;

    const float* inB = In + rBase * inRow;
    const float* wB  = Wp + cBase * 2;

#pragma unroll 1
    for (int k0 = 0; k0 < KD; k0 += 4) {
        ulonglong2 a2[8];    // a2[i].x = {k0,k0+1}, a2[i].y = {k0+2,k0+3}
#pragma unroll
        for (int i = 0; i < 8; i++)
            a2[i] = *(const ulonglong2*)(inB + i * inRow + k0);

        {   // kp = k0/2 : k values (k0, k0+1)
            const float* bp = wB + (k0 >> 1) * (NH * 2);
            ulonglong2 t0 = *(const ulonglong2*)(bp);
            ulonglong2 t1 = *(const ulonglong2*)(bp + 4);
            ulonglong2 t2 = *(const ulonglong2*)(bp + 8);
            ulonglong2 t3 = *(const ulonglong2*)(bp + 12);
            u64t b[8] = {t0.x, t0.y, t1.x, t1.y, t2.x, t2.y, t3.x, t3.y};
#pragma unroll
            for (int i = 0; i < 8; i++) {
                u64t av = a2[i].x;
#pragma unroll
                for (int j = 0; j < 8; j++) FMA_F32X2(acc[i][j], av, b[j]);
            }
        }
        {   // kp = k0/2 + 1 : k values (k0+2, k0+3)
            const float* bp = wB + ((k0 >> 1) + 1) * (NH * 2);
            ulonglong2 t0 = *(const ulonglong2*)(bp);
            ulonglong2 t1 = *(const ulonglong2*)(bp + 4);
            ulonglong2 t2 = *(const ulonglong2*)(bp + 8);
            ulonglong2 t3 = *(const ulonglong2*)(bp + 12);
            u64t b[8] = {t0.x, t0.y, t1.x, t1.y, t2.x, t2.y, t3.x, t3.y};
#pragma unroll
            for (int i = 0; i < 8; i++) {
                u64t av = a2[i].y;
#pragma unroll
                for (int j = 0; j < 8; j++) FMA_F32X2(acc[i][j], av, b[j]);
            }
        }
    }

    float4 bv0 = *(const float4*)(bias + cBase);
    float4 bv1 = *(const float4*)(bias + cBase + 4);
    float bb[8] = {bv0.x, bv0.y, bv0.z, bv0.w, bv1.x, bv1.y, bv1.z, bv1.w};

#pragma unroll
    for (int i = 0; i < 8; i++) {
        float c[8];
#pragma unroll
        for (int j = 0; j < 8; j++) {
            float lo = __uint_as_float((unsigned)(acc[i][j] & 0xffffffffull));
            float hi = __uint_as_float((unsigned)(acc[i][j] >> 32));
            c[j] = fmaxf(lo + hi + bb[j], 0.f);
        }
        float* orow = Out + (rBase + i) * outRow + cBase;
        *(float4*)(orow)     = make_float4(c[0], c[1], c[2], c[3]);
        *(float4*)(orow + 4) = make_float4(c[4], c[5], c[6], c[7]);
    }
}

__global__ void __launch_bounds__(NTHREADS, 1)
topdown_kernel(const float* __restrict__ towers,
               const float* __restrict__ aggregate,
               const float* __restrict__ M1b,
               const float* __restrict__ M2b,
               const float* __restrict__ M3b,
               const float* __restrict__ O1b,
               const float* __restrict__ O2b,
               const float* __restrict__ O3w, const float* __restrict__ O3b,
               float* __restrict__ out)
{
    extern __shared__ float smem[];
    float* X  = smem;                 // TM * XROW  (summary | tower | pad)
    float* H1 = X + TM * XROW;        // TM * NH
    float* H2 = H1 + TM * NH;         // TM * NH
    float* P  = H2 + TM * NH;         // TM running product

    const int tid = threadIdx.x;
    const size_t row0 = (size_t)blockIdx.x * TM;

    // init summary = aggregate (broadcast row), zero 2 pad cols, P = 1
    for (int i = tid; i < TM * NH; i += NTHREADS) {
        int r = i >> 8, c = i & 255;
        X[r * XROW + c] = aggregate[c];
    }
    for (int i = tid; i < TM * 2; i += NTHREADS) {
        int r = i >> 1, c = 270 + (i & 1);
        X[r * XROW + c] = 0.f;
    }
    if (tid < TM) P[tid] = 1.f;
    __syncthreads();

    for (int s = 0; s < KTOT; s++) {
        // tower slice for this step: towers[:, KTOT-1-s, :]
        for (int i = tid; i < TM * NIN; i += NTHREADS) {
            int r = i / NIN, c = i - r * NIN;
            X[r * XROW + 256 + c] =
                towers[(row0 + r) * (size_t)(KTOT * NIN)
                       + (size_t)(KTOT - 1 - s) * NIN + c];
        }
        __syncthreads();

        // ---- O path first (frees H1/H2 for M path) ----
        gemm_relu_256<XROW>(X,  XROW, g_O1wp, O1b, H1, NH, tid);
        __syncthreads();
        gemm_relu_256<NH>(H1, NH, g_O2wp, O2b, H2, NH, tid);
        __syncthreads();

        // O3: logit[r] = H2[r,:] . O3w + O3b; prod *= sigmoid(logit)
        {
            int r = tid >> 2, q = tid & 3;
            const float* h = H2 + r * NH + q * 64;
            const float* w = O3w + q * 64;
            float sum = 0.f;
#pragma unroll
            for (int k = 0; k < 64; k += 4) {
                float4 hv = *(const float4*)(h + k);
                float4 wv = *(const float4*)(w + k);
                sum = fmaf(hv.x, wv.x, sum);
                sum = fmaf(hv.y, wv.y, sum);
                sum = fmaf(hv.z, wv.z, sum);
                sum = fmaf(hv.w, wv.w, sum);
            }
            sum += __shfl_xor_sync(0xffffffffu, sum, 1);
            sum += __shfl_xor_sync(0xffffffffu, sum, 2);
            if (q == 0) {
                float logit = sum + O3b[0];
                P[r] *= 1.f / (1.f + expf(-logit));
            }
        }
        // No sync needed here: M1 writes H1 (last read before previous sync);
        // the O3 block above only touches H2/P.

        // ---- M path ----
        gemm_relu_256<XROW>(X,  XROW, g_M1wp, M1b, H1, NH, tid);
        __syncthreads();   // also fences O3's H2 reads before M2 writes H2
        gemm_relu_256<NH>(H1, NH, g_M2wp, M2b, H2, NH, tid);
        __syncthreads();
        // new summary written straight into X[:, 0:256]
        gemm_relu_256<NH>(H2, NH, g_M3wp, M3b, X, XROW, tid);
        __syncthreads();
    }

    if (tid < TM) out[row0 + tid] = P[tid];
}

extern "C" void kernel_launch(void* const* d_in, const int* in_sizes, int n_in,
                              void* d_out, int out_size)
{
    const float* towers    = (const float*)d_in[0];
    const float* aggregate = (const float*)d_in[1];
    const float* M1w = (const float*)d_in[2];
    const float* M1b = (const float*)d_in[3];
    const float* M2w = (const float*)d_in[4];
    const float* M2b = (const float*)d_in[5];
    const float* M3w = (const float*)d_in[6];
    const float* M3b = (const float*)d_in[7];
    const float* O1w = (const float*)d_in[8];
    const float* O1b = (const float*)d_in[9];
    const float* O2w = (const float*)d_in[10];
    const float* O2b = (const float*)d_in[11];
    const float* O3w = (const float*)d_in[12];
    const float* O3b = (const float*)d_in[13];
    float* out = (float*)d_out;

    const int N = in_sizes[0] / (KTOT * NIN);   // 131072

    repack_weights_kernel<<<((XROW / 2) * NH + 255) / 256, 256>>>(
        M1w, O1w, M2w, M3w, O2w);

    const size_t smem_bytes =
        (size_t)(TM * XROW + 2 * TM * NH + TM) * sizeof(float);
    cudaFuncSetAttribute(topdown_kernel,
                         cudaFuncAttributeMaxDynamicSharedMemorySize,
                         (int)smem_bytes);

    topdown_kernel<<<N / TM, NTHREADS, smem_bytes>>>(
        towers, aggregate,
        M1b, M2b, M3b,
        O1b, O2b,
        O3w, O3b,
        out);
}

// round 9
// speedup vs baseline: 1.2594x; 1.2594x over previous
#include <cuda_runtime.h>
#include <math.h>

#define NIN 14
#define NH 256
#define KTOT 10
#define TM 64
#define NTHREADS 512
#define XSTRIDE 276   // 272 used (256 summary + 14 tower + pads), mod 32 = 20 -> conflict-free
#define HSTRIDE 260   // 256 used, mod 32 = 4 -> conflict-free
#define XKP (XSTRIDE / 2)   // 138 k-pairs, pairs >=135 hit zero-padded weight rows
#define HKP (NH / 2)        // 128 k-pairs

typedef unsigned long long u64t;

// fma.rn.f32x2: d.lo += a.lo*b.lo ; d.hi += a.hi*b.hi  (sm_100+)
#define FMA_F32X2(d, a, b) \
    asm("fma.rn.f32x2 %0, %1, %2, %0;" : "+l"(d) : "l"(a), "l"(b))

// ---------------------------------------------------------------------------
// Repacked weights, k-pair interleaved: Wp[kp*512 + j*2 + t] = W[2*kp+t][j]
// First-layer weights padded 270 -> 276 rows (zeros).
// ---------------------------------------------------------------------------
__device__ __align__(16) float g_M1wp[XKP * NH * 2];
__device__ __align__(16) float g_O1wp[XKP * NH * 2];
__device__ __align__(16) float g_M2wp[HKP * NH * 2];
__device__ __align__(16) float g_M3wp[HKP * NH * 2];
__device__ __align__(16) float g_O2wp[HKP * NH * 2];

__global__ void repack_weights_kernel(const float* __restrict__ M1w,
                                      const float* __restrict__ O1w,
                                      const float* __restrict__ M2w,
                                      const float* __restrict__ M3w,
                                      const float* __restrict__ O2w) {
    int idx = blockIdx.x * blockDim.x + threadIdx.x;   // over XKP*256
    if (idx >= XKP * NH) return;
    int kp = idx >> 8;
    int j  = idx & 255;
    int k0 = 2 * kp, k1 = 2 * kp + 1;

    g_M1wp[idx * 2]     = (k0 < 270) ? M1w[k0 * NH + j] : 0.f;
    g_M1wp[idx * 2 + 1] = (k1 < 270) ? M1w[k1 * NH + j] : 0.f;
    g_O1wp[idx * 2]     = (k0 < 270) ? O1w[k0 * NH + j] : 0.f;
    g_O1wp[idx * 2 + 1] = (k1 < 270) ? O1w[k1 * NH + j] : 0.f;

    if (kp < HKP) {
        g_M2wp[idx * 2]     = M2w[k0 * NH + j];
        g_M2wp[idx * 2 + 1] = M2w[k1 * NH + j];
        g_M3wp[idx * 2]     = M3w[k0 * NH + j];
        g_M3wp[idx * 2 + 1] = M3w[k1 * NH + j];
        g_O2wp[idx * 2]     = O2w[k0 * NH + j];
        g_O2wp[idx * 2 + 1] = O2w[k1 * NH + j];
    }
}

// ---------------------------------------------------------------------------
// Packed-f32x2 GEMM: Out[64][256] = relu(In[64][2*KPD] @ W + bias)
// 512 threads. Warp tile 32r x 32c (warpRow=wid>>3, warpCol=wid&7).
// Lane: lr=lane&3, lc=lane>>2. Thread: rows {rBase+lr+4i}, cols cBase..+3.
// acc[i][j] pairs the K dim (lo=even k, hi=odd k): 64 acc registers.
// A: LDS.64, 4 distinct addrs x 8-way broadcast, conflict-free via stride pad.
// B: two 16B loads/kp, 8 distinct lanes -> 128B wavefronts, L1-resident.
// ---------------------------------------------------------------------------
template <int KPD>
__device__ __forceinline__ void gemm_relu_256(
    const float* __restrict__ In, const int inRow,
    const float* __restrict__ Wp, const float* __restrict__ bias,
    float* __restrict__ Out, const int outRow, const int tid)
{
    const int wid  = tid >> 5;
    const int lane = tid & 31;
    const int lr   = lane & 3;
    const int lc   = lane >> 2;
    const int rBase = (wid >> 3) * 32;            // + lr + 4*i
    const int cBase = (wid & 7) * 32 + lc * 4;

    u64t acc[8][4];
#pragma unroll
    for (int i = 0; i < 8; i++)
#pragma unroll
        for (int j = 0; j < 4; j++) acc[i][j] = 0ull;

    const float* aBase = In + (rBase + lr) * inRow;
    const float* bBase = Wp + cBase * 2;

#pragma unroll 1
    for (int kp = 0; kp < KPD; kp++) {
        u64t a[8];
#pragma unroll
        for (int i = 0; i < 8; i++)
            a[i] = *(const u64t*)(aBase + i * 4 * inRow + 2 * kp);

        const float* bp = bBase + kp * (NH * 2);
        ulonglong2 b01 = *(const ulonglong2*)(bp);
        ulonglong2 b23 = *(const ulonglong2*)(bp + 4);
        u64t b[4] = {b01.x, b01.y, b23.x, b23.y};

#pragma unroll
        for (int i = 0; i < 8; i++)
#pragma unroll
            for (int j = 0; j < 4; j++)
                FMA_F32X2(acc[i][j], a[i], b[j]);
    }

    float4 bv = *(const float4*)(bias + cBase);
    float bb[4] = {bv.x, bv.y, bv.z, bv.w};

#pragma unroll
    for (int i = 0; i < 8; i++) {
        float c[4];
#pragma unroll
        for (int j = 0; j < 4; j++) {
            float lo = __uint_as_float((unsigned)(acc[i][j] & 0xffffffffull));
            float hi = __uint_as_float((unsigned)(acc[i][j] >> 32));
            c[j] = fmaxf(lo + hi + bb[j], 0.f);
        }
        const int r = rBase + lr + 4 * i;
        *(float4*)(Out + r * outRow + cBase) =
            make_float4(c[0], c[1], c[2], c[3]);
    }
}

__global__ void __launch_bounds__(NTHREADS, 1)
topdown_kernel(const float* __restrict__ towers,
               const float* __restrict__ aggregate,
               const float* __restrict__ M1b,
               const float* __restrict__ M2b,
               const float* __restrict__ M3b,
               const float* __restrict__ O1b,
               const float* __restrict__ O2b,
               const float* __restrict__ O3w, const float* __restrict__ O3b,
               float* __restrict__ out)
{
    extern __shared__ float smem[];
    float* X  = smem;                      // TM * XSTRIDE
    float* H1 = X + TM * XSTRIDE;          // TM * HSTRIDE
    float* H2 = H1 + TM * HSTRIDE;         // TM * HSTRIDE
    float* P  = H2 + TM * HSTRIDE;         // TM

    const int tid = threadIdx.x;
    const size_t row0 = (size_t)blockIdx.x * TM;

    // init: summary = aggregate, pad cols (incl. tower slot) zeroed, P = 1
    for (int i = tid; i < TM * XSTRIDE; i += NTHREADS) {
        int r = i / XSTRIDE, c = i - r * XSTRIDE;
        X[i] = (c < NH) ? aggregate[c] : 0.f;
        (void)r;
    }
    if (tid < TM) P[tid] = 1.f;
    __syncthreads();

    for (int s = 0; s < KTOT; s++) {
        // tower slice for this step: towers[:, KTOT-1-s, :]
        for (int i = tid; i < TM * NIN; i += NTHREADS) {
            int r = i / NIN, c = i - r * NIN;
            X[r * XSTRIDE + 256 + c] =
                towers[(row0 + r) * (size_t)(KTOT * NIN)
                       + (size_t)(KTOT - 1 - s) * NIN + c];
        }
        __syncthreads();

        // ---- O path first (frees H1/H2 for M path) ----
        gemm_relu_256<XKP>(X,  XSTRIDE, g_O1wp, O1b, H1, HSTRIDE, tid);
        __syncthreads();
        gemm_relu_256<HKP>(H1, HSTRIDE, g_O2wp, O2b, H2, HSTRIDE, tid);
        __syncthreads();

        // O3: logit[r] = H2[r,:] . O3w + O3b; prod *= sigmoid(logit)
        {
            int r = tid >> 3, q = tid & 7;    // 8 threads per row
            const float* h = H2 + r * HSTRIDE + q * 32;
            const float* w = O3w + q * 32;
            float sum = 0.f;
#pragma unroll
            for (int k = 0; k < 32; k += 4) {
                float4 hv = *(const float4*)(h + k);
                float4 wv = *(const float4*)(w + k);
                sum = fmaf(hv.x, wv.x, sum);
                sum = fmaf(hv.y, wv.y, sum);
                sum = fmaf(hv.z, wv.z, sum);
                sum = fmaf(hv.w, wv.w, sum);
            }
            sum += __shfl_xor_sync(0xffffffffu, sum, 1);
            sum += __shfl_xor_sync(0xffffffffu, sum, 2);
            sum += __shfl_xor_sync(0xffffffffu, sum, 4);
            if (q == 0) {
                float logit = sum + O3b[0];
                P[r] *= 1.f / (1.f + expf(-logit));
            }
        }
        // No sync needed: M1 writes H1 (last read before the previous sync);
        // the O3 block above only touches H2/P.

        // ---- M path ----
        gemm_relu_256<XKP>(X,  XSTRIDE, g_M1wp, M1b, H1, HSTRIDE, tid);
        __syncthreads();   // also fences O3's H2 reads before M2 writes H2
        gemm_relu_256<HKP>(H1, HSTRIDE, g_M2wp, M2b, H2, HSTRIDE, tid);
        __syncthreads();
        // new summary written straight into X[:, 0:256]
        gemm_relu_256<HKP>(H2, HSTRIDE, g_M3wp, M3b, X, XSTRIDE, tid);
        __syncthreads();
    }

    if (tid < TM) out[row0 + tid] = P[tid];
}

extern "C" void kernel_launch(void* const* d_in, const int* in_sizes, int n_in,
                              void* d_out, int out_size)
{
    const float* towers    = (const float*)d_in[0];
    const float* aggregate = (const float*)d_in[1];
    const float* M1w = (const float*)d_in[2];
    const float* M1b = (const float*)d_in[3];
    const float* M2w = (const float*)d_in[4];
    const float* M2b = (const float*)d_in[5];
    const float* M3w = (const float*)d_in[6];
    const float* M3b = (const float*)d_in[7];
    const float* O1w = (const float*)d_in[8];
    const float* O1b = (const float*)d_in[9];
    const float* O2w = (const float*)d_in[10];
    const float* O2b = (const float*)d_in[11];
    const float* O3w = (const float*)d_in[12];
    const float* O3b = (const float*)d_in[13];
    float* out = (float*)d_out;

    const int N = in_sizes[0] / (KTOT * NIN);   // 131072

    repack_weights_kernel<<<(XKP * NH + 255) / 256, 256>>>(
        M1w, O1w, M2w, M3w, O2w);

    const size_t smem_bytes =
        (size_t)(TM * XSTRIDE + 2 * TM * HSTRIDE + TM) * sizeof(float);
    cudaFuncSetAttribute(topdown_kernel,
                         cudaFuncAttributeMaxDynamicSharedMemorySize,
                         (int)smem_bytes);

    topdown_kernel<<<N / TM, NTHREADS, smem_bytes>>>(
        towers, aggregate,
        M1b, M2b, M3b,
        O1b, O2b,
        O3w, O3b,
        out);
}

// round 10
// speedup vs baseline: 3.1622x; 2.5109x over previous
#include <cuda_runtime.h>
#include <cuda_bf16.h>
#include <math.h>

#define NIN 14
#define NH 256
#define KTOT 10
#define TM 64
#define NTHREADS 256
#define KKX 17              // k-steps for 272-wide input (256 summary + 14 tower + 2 pad)
#define KKH 16              // k-steps for 256-wide hidden
#define XWORDS (4 * KKX * 4 * 32)   // 8704 uint2
#define HWORDS (4 * KKH * 4 * 32)   // 8192 uint2

// ---------------------------------------------------------------------------
// Split helpers: value = hi(bf16) + lo(bf16), error ~2^-17 relative.
// Word packs a k-pair: low 16 bits = even-k element, high = odd-k.
// uint2: .x = hi-pair word, .y = lo-pair word.
// ---------------------------------------------------------------------------
__device__ __forceinline__ uint2 split2(float v0, float v1) {
    __nv_bfloat16 h0 = __float2bfloat16_rn(v0);
    __nv_bfloat16 h1 = __float2bfloat16_rn(v1);
    __nv_bfloat16 l0 = __float2bfloat16_rn(v0 - __bfloat162float(h0));
    __nv_bfloat16 l1 = __float2bfloat16_rn(v1 - __bfloat162float(h1));
    uint2 w;
    w.x = (unsigned)__bfloat16_as_ushort(h0) |
          ((unsigned)__bfloat16_as_ushort(h1) << 16);
    w.y = (unsigned)__bfloat16_as_ushort(l0) |
          ((unsigned)__bfloat16_as_ushort(l1) << 16);
    return w;
}
__device__ __forceinline__ float bf_lo(unsigned w) {
    return __bfloat162float(__ushort_as_bfloat16((unsigned short)(w & 0xffffu)));
}
__device__ __forceinline__ float bf_hi(unsigned w) {
    return __bfloat162float(__ushort_as_bfloat16((unsigned short)(w >> 16)));
}

// ---------------------------------------------------------------------------
// Fragment-major weight arrays, built once by prep kernel.
// Index: ((kk*32 + ntg)*2 + slot)*32 + lane
//   content: cols = ntg*8 + (lane>>2), k0 = kk*16 + slot*8 + 2*(lane&3)
//   word = { W[k0][col], W[k0+1][col] }  (hi pair in .x, lo pair in .y)
// ---------------------------------------------------------------------------
__device__ __align__(16) uint2 g_M1[KKX * 2048];
__device__ __align__(16) uint2 g_O1[KKX * 2048];
__device__ __align__(16) uint2 g_M2[KKH * 2048];
__device__ __align__(16) uint2 g_M3[KKH * 2048];
__device__ __align__(16) uint2 g_O2[KKH * 2048];

__global__ void prep_weights(const float* __restrict__ M1w,
                             const float* __restrict__ O1w,
                             const float* __restrict__ M2w,
                             const float* __restrict__ M3w,
                             const float* __restrict__ O2w) {
    int w = blockIdx.x * blockDim.x + threadIdx.x;
    if (w >= KKX * 2048) return;
    int kk   = w >> 11;
    int rem  = w & 2047;
    int ntg  = rem >> 6;
    int slot = (rem >> 5) & 1;
    int lane = rem & 31;
    int k0   = kk * 16 + slot * 8 + 2 * (lane & 3);
    int col  = ntg * 8 + (lane >> 2);

    float a0 = (k0     < 270) ? M1w[k0 * NH + col]       : 0.f;
    float a1 = (k0 + 1 < 270) ? M1w[(k0 + 1) * NH + col] : 0.f;
    g_M1[w] = split2(a0, a1);
    a0 = (k0     < 270) ? O1w[k0 * NH + col]       : 0.f;
    a1 = (k0 + 1 < 270) ? O1w[(k0 + 1) * NH + col] : 0.f;
    g_O1[w] = split2(a0, a1);

    if (kk < KKH) {   // k0+1 <= 255 here
        g_M2[w] = split2(M2w[k0 * NH + col], M2w[(k0 + 1) * NH + col]);
        g_M3[w] = split2(M3w[k0 * NH + col], M3w[(k0 + 1) * NH + col]);
        g_O2[w] = split2(O2w[k0 * NH + col], O2w[(k0 + 1) * NH + col]);
    }
}

// ---------------------------------------------------------------------------
// mma.sync m16n8k16 bf16, fp32 accumulate
// ---------------------------------------------------------------------------
__device__ __forceinline__ void mma16816(float c[4], const unsigned a[4],
                                         unsigned b0, unsigned b1) {
    asm("mma.sync.aligned.m16n8k16.row.col.f32.bf16.bf16.f32 "
        "{%0,%1,%2,%3}, {%4,%5,%6,%7}, {%8,%9}, {%0,%1,%2,%3};"
        : "+f"(c[0]), "+f"(c[1]), "+f"(c[2]), "+f"(c[3])
        : "r"(a[0]), "r"(a[1]), "r"(a[2]), "r"(a[3]), "r"(b0), "r"(b1));
}

// ---------------------------------------------------------------------------
// One layer: O[64][256] = relu(A[64][16*kSteps] @ W + bias), split-bf16 3-MMA.
// Activation buffers are fragment-major uint2 arrays in SMEM:
//   idx(mt, kk, slot, lane) = ((mt*KKS + kk)*4 + slot)*32 + lane
//   word = rows r = mt*16 + (lane>>2) + (slot&1)*8,
//          k-pair kp = kk*8 + (slot>>1)*4 + (lane&3)  -> elements A[r,2kp],A[r,2kp+1]
// Warp grid: wm = wid>>2 (2 x 32 rows), wn = wid&3 (4 x 64 cols).
// ---------------------------------------------------------------------------
__device__ __forceinline__ void gemm_layer(
    const uint2* __restrict__ A, int aKKS, int kSteps,
    const uint2* __restrict__ WB, const float* __restrict__ bias,
    uint2* __restrict__ O, int oKKS, int tid)
{
    const int wid  = tid >> 5;
    const int lane = tid & 31;
    const int wm = wid >> 2;
    const int wn = wid & 3;
    const int t  = lane & 3;

    float c[2][8][4];
#pragma unroll
    for (int m = 0; m < 2; m++)
#pragma unroll
        for (int nt = 0; nt < 8; nt++)
#pragma unroll
            for (int i = 0; i < 4; i++) c[m][nt][i] = 0.f;

    const uint2* a0p = A + (wm * 2 + 0) * aKKS * 128 + lane;
    const uint2* a1p = A + (wm * 2 + 1) * aKKS * 128 + lane;
    const uint2* wp  = WB + (wn * 8) * 64 + lane;

#pragma unroll 1
    for (int kk = 0; kk < kSteps; kk++) {
        unsigned ah[2][4], al[2][4];
#pragma unroll
        for (int s = 0; s < 4; s++) {
            uint2 w0 = a0p[kk * 128 + s * 32];
            uint2 w1 = a1p[kk * 128 + s * 32];
            ah[0][s] = w0.x; al[0][s] = w0.y;
            ah[1][s] = w1.x; al[1][s] = w1.y;
        }
        unsigned bh[8][2], bl[8][2];
        const uint2* wk = wp + kk * 2048;
#pragma unroll
        for (int nt = 0; nt < 8; nt++) {
            uint2 w0 = wk[nt * 64];
            uint2 w1 = wk[nt * 64 + 32];
            bh[nt][0] = w0.x; bl[nt][0] = w0.y;
            bh[nt][1] = w1.x; bl[nt][1] = w1.y;
        }
#pragma unroll
        for (int m = 0; m < 2; m++)
#pragma unroll
            for (int nt = 0; nt < 8; nt++) {
                mma16816(c[m][nt], ah[m], bh[nt][0], bh[nt][1]);  // hi*hi
                mma16816(c[m][nt], ah[m], bl[nt][0], bl[nt][1]);  // hi*lo
                mma16816(c[m][nt], al[m], bh[nt][0], bh[nt][1]);  // lo*hi
            }
    }

    // Epilogue: bias + relu + split, stored straight into the next layer's
    // A-fragment layout. Writer word (c0,c1) -> (row g), (c2,c3) -> (row g+8);
    // kk_out = wn*4 + (nt>>1), slot = (nt&1)*2 (+1 for row+8); lane unchanged.
#pragma unroll
    for (int m = 0; m < 2; m++)
#pragma unroll
        for (int nt = 0; nt < 8; nt++) {
            int col = wn * 64 + nt * 8 + 2 * t;
            float2 bv = *(const float2*)(bias + col);
            float v0 = fmaxf(c[m][nt][0] + bv.x, 0.f);
            float v1 = fmaxf(c[m][nt][1] + bv.y, 0.f);
            float v2 = fmaxf(c[m][nt][2] + bv.x, 0.f);
            float v3 = fmaxf(c[m][nt][3] + bv.y, 0.f);
            int mt   = wm * 2 + m;
            int kko  = wn * 4 + (nt >> 1);
            int slot = (nt & 1) * 2;
            O[((mt * oKKS + kko) * 4 + slot    ) * 32 + lane] = split2(v0, v1);
            O[((mt * oKKS + kko) * 4 + slot + 1) * 32 + lane] = split2(v2, v3);
        }
}

__global__ void __launch_bounds__(NTHREADS, 1)
topdown_kernel(const float* __restrict__ towers,
               const float* __restrict__ aggregate,
               const float* __restrict__ M1b,
               const float* __restrict__ M2b,
               const float* __restrict__ M3b,
               const float* __restrict__ O1b,
               const float* __restrict__ O2b,
               const float* __restrict__ O3w, const float* __restrict__ O3b,
               float* __restrict__ out)
{
    extern __shared__ uint2 smem2[];
    uint2* X  = smem2;            // XWORDS
    uint2* H1 = X + XWORDS;       // HWORDS
    uint2* H2 = H1 + HWORDS;      // HWORDS
    float* P  = (float*)(H2 + HWORDS);

    const int tid = threadIdx.x;
    const size_t row0 = (size_t)blockIdx.x * TM;

    // init summary region of X (kk 0..15) from aggregate (row-broadcast), P=1
    for (int w = tid; w < 4 * KKH * 4 * 32; w += NTHREADS) {
        int mt   = w >> 11;
        int rem  = w & 2047;
        int kk   = rem >> 7;
        int rem2 = rem & 127;
        int slot = rem2 >> 5;
        int lane = rem2 & 31;
        int kp   = kk * 8 + (slot >> 1) * 4 + (lane & 3);
        X[((mt * KKX + kk) * 4 + slot) * 32 + lane] =
            split2(aggregate[2 * kp], aggregate[2 * kp + 1]);
    }
    if (tid < TM) P[tid] = 1.f;
    __syncthreads();

    for (int s = 0; s < KTOT; s++) {
        // fill tower region of X (kk == 16): k = 256..271, zeros past 269
        for (int w = tid; w < 512; w += NTHREADS) {
            int mt   = w >> 7;
            int rem  = w & 127;
            int slot = rem >> 5;
            int lane = rem & 31;
            int r = mt * 16 + (lane >> 2) + (slot & 1) * 8;
            int k = 256 + (slot >> 1) * 8 + 2 * (lane & 3);
            const float* tp = towers + (row0 + r) * (size_t)(KTOT * NIN)
                                     + (size_t)(KTOT - 1 - s) * NIN;
            float v0 = (k     < 270) ? tp[k - 256]     : 0.f;
            float v1 = (k + 1 < 270) ? tp[k + 1 - 256] : 0.f;
            X[((mt * KKX + 16) * 4 + slot) * 32 + lane] = split2(v0, v1);
        }
        __syncthreads();

        // ---- O path ----
        gemm_layer(X,  KKX, KKX, g_O1, O1b, H1, KKH, tid);
        __syncthreads();
        gemm_layer(H1, KKH, KKH, g_O2, O2b, H2, KKH, tid);
        __syncthreads();

        // O3: logit[r] = H2[r,:] . O3w + O3b ; P[r] *= sigmoid(logit)
        {
            int r = tid >> 2, q = tid & 3;
            int mt = r >> 4;
            int rloc = r & 15;
            int g = rloc & 7;
            int rowhi = rloc >> 3;
            float sum = 0.f;
#pragma unroll 4
            for (int kp = q * 32; kp < q * 32 + 32; kp++) {
                int kk   = kp >> 3;
                int slot = ((kp >> 2) & 1) * 2 + rowhi;
                int lane = g * 4 + (kp & 3);
                uint2 wv = H2[((mt * KKH + kk) * 4 + slot) * 32 + lane];
                float v0 = bf_lo(wv.x) + bf_lo(wv.y);
                float v1 = bf_hi(wv.x) + bf_hi(wv.y);
                float2 ww = *(const float2*)(O3w + 2 * kp);
                sum = fmaf(v0, ww.x, fmaf(v1, ww.y, sum));
            }
            sum += __shfl_xor_sync(0xffffffffu, sum, 1);
            sum += __shfl_xor_sync(0xffffffffu, sum, 2);
            if (q == 0) {
                float logit = sum + O3b[0];
                P[r] *= 1.f / (1.f + expf(-logit));
            }
        }
        // No sync needed: M1 below writes H1 (last read before prior sync);
        // the O3 block only reads H2 / writes P.

        // ---- M path ----
        gemm_layer(X,  KKX, KKX, g_M1, M1b, H1, KKH, tid);
        __syncthreads();   // fences O3's H2 reads before M2 writes H2
        gemm_layer(H1, KKH, KKH, g_M2, M2b, H2, KKH, tid);
        __syncthreads();
        gemm_layer(H2, KKH, KKH, g_M3, M3b, X, KKX, tid);  // summary -> X kk 0..15
        __syncthreads();
    }

    if (tid < TM) out[row0 + tid] = P[tid];
}

extern "C" void kernel_launch(void* const* d_in, const int* in_sizes, int n_in,
                              void* d_out, int out_size)
{
    const float* towers    = (const float*)d_in[0];
    const float* aggregate = (const float*)d_in[1];
    const float* M1w = (const float*)d_in[2];
    const float* M1b = (const float*)d_in[3];
    const float* M2w = (const float*)d_in[4];
    const float* M2b = (const float*)d_in[5];
    const float* M3w = (const float*)d_in[6];
    const float* M3b = (const float*)d_in[7];
    const float* O1w = (const float*)d_in[8];
    const float* O1b = (const float*)d_in[9];
    const float* O2w = (const float*)d_in[10];
    const float* O2b = (const float*)d_in[11];
    const float* O3w = (const float*)d_in[12];
    const float* O3b = (const float*)d_in[13];
    float* out = (float*)d_out;

    const int N = in_sizes[0] / (KTOT * NIN);   // 131072

    prep_weights<<<(KKX * 2048 + 255) / 256, 256>>>(M1w, O1w, M2w, M3w, O2w);

    const size_t smem_bytes =
        (size_t)(XWORDS + 2 * HWORDS) * sizeof(uint2) + TM * sizeof(float);
    cudaFuncSetAttribute(topdown_kernel,
                         cudaFuncAttributeMaxDynamicSharedMemorySize,
                         (int)smem_bytes);

    topdown_kernel<<<N / TM, NTHREADS, smem_bytes>>>(
        towers, aggregate,
        M1b, M2b, M3b,
        O1b, O2b,
        O3w, O3b,
        out);
}

// round 14
// speedup vs baseline: 4.1674x; 1.3179x over previous
#include <cuda_runtime.h>
#include <cuda_bf16.h>
#include <math.h>

#define NIN 14
#define NH 256
#define KTOT 10
#define TM 32
#define NTHREADS 256
#define KKX 17              // k-steps for 272-wide input (256 summary + 14 tower + 2 pad)
#define KKH 16              // k-steps for 256-wide hidden
#define XWORDS (2 * KKX * 4 * 32)   // 4352 uint2 (TM/16 = 2 m-tiles)
#define HWORDS (2 * KKH * 4 * 32)   // 4096 uint2

// ---------------------------------------------------------------------------
// Split helpers: value = hi(bf16) + lo(bf16), error ~2^-17 relative.
// Word packs a k-pair: low 16 bits = even-k element, high = odd-k.
// uint2: .x = hi-pair word, .y = lo-pair word.
// ---------------------------------------------------------------------------
__device__ __forceinline__ uint2 split2(float v0, float v1) {
    __nv_bfloat16 h0 = __float2bfloat16_rn(v0);
    __nv_bfloat16 h1 = __float2bfloat16_rn(v1);
    __nv_bfloat16 l0 = __float2bfloat16_rn(v0 - __bfloat162float(h0));
    __nv_bfloat16 l1 = __float2bfloat16_rn(v1 - __bfloat162float(h1));
    uint2 w;
    w.x = (unsigned)__bfloat16_as_ushort(h0) |
          ((unsigned)__bfloat16_as_ushort(h1) << 16);
    w.y = (unsigned)__bfloat16_as_ushort(l0) |
          ((unsigned)__bfloat16_as_ushort(l1) << 16);
    return w;
}
__device__ __forceinline__ float bf_lo(unsigned w) {
    return __bfloat162float(__ushort_as_bfloat16((unsigned short)(w & 0xffffu)));
}
__device__ __forceinline__ float bf_hi(unsigned w) {
    return __bfloat162float(__ushort_as_bfloat16((unsigned short)(w >> 16)));
}

// ---------------------------------------------------------------------------
// Fragment-major weight arrays (built once).
// Index: ((kk*32 + ntg)*2 + slot)*32 + lane
//   cols = ntg*8 + (lane>>2), k0 = kk*16 + slot*8 + 2*(lane&3)
//   word = { W[k0][col], W[k0+1][col] }  (hi pair in .x, lo pair in .y)
// ---------------------------------------------------------------------------
__device__ __align__(16) uint2 g_M1[KKX * 2048];
__device__ __align__(16) uint2 g_O1[KKX * 2048];
__device__ __align__(16) uint2 g_M2[KKH * 2048];
__device__ __align__(16) uint2 g_M3[KKH * 2048];
__device__ __align__(16) uint2 g_O2[KKH * 2048];

__global__ void prep_weights(const float* __restrict__ M1w,
                             const float* __restrict__ O1w,
                             const float* __restrict__ M2w,
                             const float* __restrict__ M3w,
                             const float* __restrict__ O2w) {
    int w = blockIdx.x * blockDim.x + threadIdx.x;
    if (w >= KKX * 2048) return;
    int kk   = w >> 11;
    int rem  = w & 2047;
    int ntg  = rem >> 6;
    int slot = (rem >> 5) & 1;
    int lane = rem & 31;
    int k0   = kk * 16 + slot * 8 + 2 * (lane & 3);
    int col  = ntg * 8 + (lane >> 2);

    float a0 = (k0     < 270) ? M1w[k0 * NH + col]       : 0.f;
    float a1 = (k0 + 1 < 270) ? M1w[(k0 + 1) * NH + col] : 0.f;
    g_M1[w] = split2(a0, a1);
    a0 = (k0     < 270) ? O1w[k0 * NH + col]       : 0.f;
    a1 = (k0 + 1 < 270) ? O1w[(k0 + 1) * NH + col] : 0.f;
    g_O1[w] = split2(a0, a1);

    if (kk < KKH) {
        g_M2[w] = split2(M2w[k0 * NH + col], M2w[(k0 + 1) * NH + col]);
        g_M3[w] = split2(M3w[k0 * NH + col], M3w[(k0 + 1) * NH + col]);
        g_O2[w] = split2(O2w[k0 * NH + col], O2w[(k0 + 1) * NH + col]);
    }
}

__device__ __forceinline__ void mma16816(float c[4], const unsigned a[4],
                                         unsigned b0, unsigned b1) {
    asm("mma.sync.aligned.m16n8k16.row.col.f32.bf16.bf16.f32 "
        "{%0,%1,%2,%3}, {%4,%5,%6,%7}, {%8,%9}, {%0,%1,%2,%3};"
        : "+f"(c[0]), "+f"(c[1]), "+f"(c[2]), "+f"(c[3])
        : "r"(a[0]), "r"(a[1]), "r"(a[2]), "r"(a[3]), "r"(b0), "r"(b1));
}

// ---------------------------------------------------------------------------
// One layer: O[32][256] = relu(A[32][16*kSteps] @ W + bias), split-bf16 3-MMA.
// Activation buffers, fragment-major uint2:
//   idx(mt, kk, slot, lane) = ((mt*KKS + kk)*4 + slot)*32 + lane
//   rows r = mt*16 + (lane>>2) + (slot&1)*8,
//   k-pair kp = kk*8 + (slot>>1)*4 + (lane&3) -> A[r,2kp], A[r,2kp+1]
// 8 warps; warp wn = wid covers cols wn*32..+31 (4 n-tiles), all 32 rows.
// ---------------------------------------------------------------------------
__device__ __forceinline__ void gemm_layer(
    const uint2* __restrict__ A, int aKKS, int kSteps,
    const uint2* __restrict__ WB, const float* __restrict__ bias,
    uint2* __restrict__ O, int oKKS, int tid)
{
    const int wn   = tid >> 5;
    const int lane = tid & 31;
    const int t    = lane & 3;

    float c[2][4][4];
#pragma unroll
    for (int m = 0; m < 2; m++)
#pragma unroll
        for (int nt = 0; nt < 4; nt++)
#pragma unroll
            for (int i = 0; i < 4; i++) c[m][nt][i] = 0.f;

    const uint2* a0p = A + lane;                  // mt = 0
    const uint2* a1p = A + aKKS * 128 + lane;     // mt = 1
    const uint2* wp  = WB + (wn * 4) * 64 + lane;

#pragma unroll 1
    for (int kk = 0; kk < kSteps; kk++) {
        unsigned ah[2][4], al[2][4];
#pragma unroll
        for (int s = 0; s < 4; s++) {
            uint2 w0 = a0p[kk * 128 + s * 32];
            uint2 w1 = a1p[kk * 128 + s * 32];
            ah[0][s] = w0.x; al[0][s] = w0.y;
            ah[1][s] = w1.x; al[1][s] = w1.y;
        }
        unsigned bh[4][2], bl[4][2];
        const uint2* wk = wp + kk * 2048;
#pragma unroll
        for (int nt = 0; nt < 4; nt++) {
            uint2 w0 = wk[nt * 64];
            uint2 w1 = wk[nt * 64 + 32];
            bh[nt][0] = w0.x; bl[nt][0] = w0.y;
            bh[nt][1] = w1.x; bl[nt][1] = w1.y;
        }
#pragma unroll
        for (int m = 0; m < 2; m++)
#pragma unroll
            for (int nt = 0; nt < 4; nt++) {
                mma16816(c[m][nt], ah[m], bh[nt][0], bh[nt][1]);  // hi*hi
                mma16816(c[m][nt], ah[m], bl[nt][0], bl[nt][1]);  // hi*lo
                mma16816(c[m][nt], al[m], bh[nt][0], bh[nt][1]);  // lo*hi
            }
    }

    // Epilogue: bias + relu + split -> next layer's A-fragment layout.
    // (c0,c1) -> row g, (c2,c3) -> row g+8; kko = wn*2 + (nt>>1),
    // slot = (nt&1)*2 (+1 for row+8); lane unchanged.
#pragma unroll
    for (int m = 0; m < 2; m++)
#pragma unroll
        for (int nt = 0; nt < 4; nt++) {
            int col = wn * 32 + nt * 8 + 2 * t;
            float2 bv = *(const float2*)(bias + col);
            float v0 = fmaxf(c[m][nt][0] + bv.x, 0.f);
            float v1 = fmaxf(c[m][nt][1] + bv.y, 0.f);
            float v2 = fmaxf(c[m][nt][2] + bv.x, 0.f);
            float v3 = fmaxf(c[m][nt][3] + bv.y, 0.f);
            int kko  = wn * 2 + (nt >> 1);
            int slot = (nt & 1) * 2;
            O[((m * oKKS + kko) * 4 + slot    ) * 32 + lane] = split2(v0, v1);
            O[((m * oKKS + kko) * 4 + slot + 1) * 32 + lane] = split2(v2, v3);
        }
}

__global__ void __launch_bounds__(NTHREADS, 2)
topdown_kernel(const float* __restrict__ towers,
               const float* __restrict__ aggregate,
               const float* __restrict__ M1b,
               const float* __restrict__ M2b,
               const float* __restrict__ M3b,
               const float* __restrict__ O1b,
               const float* __restrict__ O2b,
               const float* __restrict__ O3w, const float* __restrict__ O3b,
               float* __restrict__ out)
{
    extern __shared__ uint2 smem2[];
    uint2* X  = smem2;            // XWORDS
    uint2* H1 = X + XWORDS;       // HWORDS
    uint2* H2 = H1 + HWORDS;      // HWORDS
    float* P  = (float*)(H2 + HWORDS);

    const int tid = threadIdx.x;
    const size_t row0 = (size_t)blockIdx.x * TM;

    // init summary region of X (kk 0..15) from aggregate (row-broadcast), P=1
    for (int w = tid; w < 2 * KKH * 4 * 32; w += NTHREADS) {
        int mt   = w >> 11;
        int rem  = w & 2047;
        int kk   = rem >> 7;
        int rem2 = rem & 127;
        int slot = rem2 >> 5;
        int lane = rem2 & 31;
        int kp   = kk * 8 + (slot >> 1) * 4 + (lane & 3);
        X[((mt * KKX + kk) * 4 + slot) * 32 + lane] =
            split2(aggregate[2 * kp], aggregate[2 * kp + 1]);
    }
    if (tid < TM) P[tid] = 1.f;
    __syncthreads();

    for (int s = 0; s < KTOT; s++) {
        // fill tower region of X (kk == 16): k = 256..271, zeros past 269
        for (int w = tid; w < 256; w += NTHREADS) {
            int mt   = w >> 7;
            int rem  = w & 127;
            int slot = rem >> 5;
            int lane = rem & 31;
            int r = mt * 16 + (lane >> 2) + (slot & 1) * 8;
            int k = 256 + (slot >> 1) * 8 + 2 * (lane & 3);
            const float* tp = towers + (row0 + r) * (size_t)(KTOT * NIN)
                                     + (size_t)(KTOT - 1 - s) * NIN;
            float v0 = (k     < 270) ? tp[k - 256]     : 0.f;
            float v1 = (k + 1 < 270) ? tp[k + 1 - 256] : 0.f;
            X[((mt * KKX + 16) * 4 + slot) * 32 + lane] = split2(v0, v1);
        }
        __syncthreads();

        // ---- O path ----
        gemm_layer(X,  KKX, KKX, g_O1, O1b, H1, KKH, tid);
        __syncthreads();
        gemm_layer(H1, KKH, KKH, g_O2, O2b, H2, KKH, tid);
        __syncthreads();

        // O3: logit[r] = H2[r,:] . O3w + O3b ; P[r] *= sigmoid(logit)
        {
            int r = tid >> 3, q = tid & 7;     // 8 threads per row, 16 kp each
            int mt = r >> 4;
            int rloc = r & 15;
            int g = rloc & 7;
            int rowhi = rloc >> 3;
            float sum = 0.f;
#pragma unroll 4
            for (int kp = q * 16; kp < q * 16 + 16; kp++) {
                int kk   = kp >> 3;
                int slot = ((kp >> 2) & 1) * 2 + rowhi;
                int lane = g * 4 + (kp & 3);
                uint2 wv = H2[((mt * KKH + kk) * 4 + slot) * 32 + lane];
                float v0 = bf_lo(wv.x) + bf_lo(wv.y);
                float v1 = bf_hi(wv.x) + bf_hi(wv.y);
                float2 ww = *(const float2*)(O3w + 2 * kp);
                sum = fmaf(v0, ww.x, fmaf(v1, ww.y, sum));
            }
            sum += __shfl_xor_sync(0xffffffffu, sum, 1);
            sum += __shfl_xor_sync(0xffffffffu, sum, 2);
            sum += __shfl_xor_sync(0xffffffffu, sum, 4);
            if (q == 0) {
                float logit = sum + O3b[0];
                P[r] *= 1.f / (1.f + expf(-logit));
            }
        }
        // No sync needed: M1 below writes H1 (last read before prior sync);
        // the O3 block only reads H2 / writes P.

        // ---- M path ----
        gemm_layer(X,  KKX, KKX, g_M1, M1b, H1, KKH, tid);
        __syncthreads();   // fences O3's H2 reads before M2 writes H2
        gemm_layer(H1, KKH, KKH, g_M2, M2b, H2, KKH, tid);
        __syncthreads();
        gemm_layer(H2, KKH, KKH, g_M3, M3b, X, KKX, tid);  // summary -> X kk 0..15
        __syncthreads();
    }

    if (tid < TM) out[row0 + tid] = P[tid];
}

extern "C" void kernel_launch(void* const* d_in, const int* in_sizes, int n_in,
                              void* d_out, int out_size)
{
    const float* towers    = (const float*)d_in[0];
    const float* aggregate = (const float*)d_in[1];
    const float* M1w = (const float*)d_in[2];
    const float* M1b = (const float*)d_in[3];
    const float* M2w = (const float*)d_in[4];
    const float* M2b = (const float*)d_in[5];
    const float* M3w = (const float*)d_in[6];
    const float* M3b = (const float*)d_in[7];
    const float* O1w = (const float*)d_in[8];
    const float* O1b = (const float*)d_in[9];
    const float* O2w = (const float*)d_in[10];
    const float* O2b = (const float*)d_in[11];
    const float* O3w = (const float*)d_in[12];
    const float* O3b = (const float*)d_in[13];
    float* out = (float*)d_out;

    const int N = in_sizes[0] / (KTOT * NIN);   // 131072

    prep_weights<<<(KKX * 2048 + 255) / 256, 256>>>(M1w, O1w, M2w, M3w, O2w);

    const size_t smem_bytes =
        (size_t)(XWORDS + 2 * HWORDS) * sizeof(uint2) + TM * sizeof(float);
    cudaFuncSetAttribute(topdown_kernel,
                         cudaFuncAttributeMaxDynamicSharedMemorySize,
                         (int)smem_bytes);

    topdown_kernel<<<N / TM, NTHREADS, smem_bytes>>>(
        towers, aggregate,
        M1b, M2b, M3b,
        O1b, O2b,
        O3w, O3b,
        out);
}

// round 15
// speedup vs baseline: 4.3191x; 1.0364x over previous
#include <cuda_runtime.h>
#include <cuda_bf16.h>
#include <math.h>

#define NIN 14
#define NH 256
#define KTOT 10
#define TM 32
#define NTHREADS 256
#define KKX 17              // k-steps for 272-wide input (256 summary + 14 tower + 2 pad)
#define KKH 16              // k-steps for 256-wide hidden
#define XWORDS (2 * KKX * 4 * 32)   // 4352 uint2 (TM/16 = 2 m-tiles)
#define HWORDS (2 * KKH * 4 * 32)   // 4096 uint2

// ---------------------------------------------------------------------------
// Fast split: value = hi(bf16) + lo(bf16), identical results to the RN/RN
// two-step split (hi = RN(v); lo = RN(v - hi)), but 6 ops per pair via
// cvt.rn.bf16x2.f32. Word packs a k-pair: low 16 = even-k, high 16 = odd-k.
// uint2: .x = hi-pair word, .y = lo-pair word.
// ---------------------------------------------------------------------------
__device__ __forceinline__ uint2 split2(float v0, float v1) {
    uint2 w;
    asm("cvt.rn.bf16x2.f32 %0, %1, %2;" : "=r"(w.x) : "f"(v1), "f"(v0));
    float h0 = __uint_as_float(w.x << 16);
    float h1 = __uint_as_float(w.x & 0xffff0000u);
    float r0 = v0 - h0;                 // exact (Sterbenz)
    float r1 = v1 - h1;
    asm("cvt.rn.bf16x2.f32 %0, %1, %2;" : "=r"(w.y) : "f"(r1), "f"(r0));
    return w;
}
__device__ __forceinline__ float bf_lo(unsigned w) {
    return __uint_as_float(w << 16);
}
__device__ __forceinline__ float bf_hi(unsigned w) {
    return __uint_as_float(w & 0xffff0000u);
}

// ---------------------------------------------------------------------------
// Fragment-major weight arrays (built once).
// Index: ((kk*32 + ntg)*2 + slot)*32 + lane
//   cols = ntg*8 + (lane>>2), k0 = kk*16 + slot*8 + 2*(lane&3)
//   word = { W[k0][col], W[k0+1][col] }  (hi pair in .x, lo pair in .y)
// ---------------------------------------------------------------------------
__device__ __align__(16) uint2 g_M1[KKX * 2048];
__device__ __align__(16) uint2 g_O1[KKX * 2048];
__device__ __align__(16) uint2 g_M2[KKH * 2048];
__device__ __align__(16) uint2 g_M3[KKH * 2048];
__device__ __align__(16) uint2 g_O2[KKH * 2048];

__global__ void prep_weights(const float* __restrict__ M1w,
                             const float* __restrict__ O1w,
                             const float* __restrict__ M2w,
                             const float* __restrict__ M3w,
                             const float* __restrict__ O2w) {
    int w = blockIdx.x * blockDim.x + threadIdx.x;
    if (w >= KKX * 2048) return;
    int kk   = w >> 11;
    int rem  = w & 2047;
    int ntg  = rem >> 6;
    int slot = (rem >> 5) & 1;
    int lane = rem & 31;
    int k0   = kk * 16 + slot * 8 + 2 * (lane & 3);
    int col  = ntg * 8 + (lane >> 2);

    float a0 = (k0     < 270) ? M1w[k0 * NH + col]       : 0.f;
    float a1 = (k0 + 1 < 270) ? M1w[(k0 + 1) * NH + col] : 0.f;
    g_M1[w] = split2(a0, a1);
    a0 = (k0     < 270) ? O1w[k0 * NH + col]       : 0.f;
    a1 = (k0 + 1 < 270) ? O1w[(k0 + 1) * NH + col] : 0.f;
    g_O1[w] = split2(a0, a1);

    if (kk < KKH) {
        g_M2[w] = split2(M2w[k0 * NH + col], M2w[(k0 + 1) * NH + col]);
        g_M3[w] = split2(M3w[k0 * NH + col], M3w[(k0 + 1) * NH + col]);
        g_O2[w] = split2(O2w[k0 * NH + col], O2w[(k0 + 1) * NH + col]);
    }
}

__device__ __forceinline__ void mma16816(float c[4], const unsigned a[4],
                                         unsigned b0, unsigned b1) {
    asm("mma.sync.aligned.m16n8k16.row.col.f32.bf16.bf16.f32 "
        "{%0,%1,%2,%3}, {%4,%5,%6,%7}, {%8,%9}, {%0,%1,%2,%3};"
        : "+f"(c[0]), "+f"(c[1]), "+f"(c[2]), "+f"(c[3])
        : "r"(a[0]), "r"(a[1]), "r"(a[2]), "r"(a[3]), "r"(b0), "r"(b1));
}

// ---------------------------------------------------------------------------
// One layer: O[32][256] = relu(A[32][16*kSteps] @ W + bias), split-bf16 3-MMA.
// Activation buffers, fragment-major uint2:
//   idx(mt, kk, slot, lane) = ((mt*KKS + kk)*4 + slot)*32 + lane
//   rows r = mt*16 + (lane>>2) + (slot&1)*8,
//   k-pair kp = kk*8 + (slot>>1)*4 + (lane&3) -> A[r,2kp], A[r,2kp+1]
// 8 warps; warp wn covers cols wn*32..+31 (4 n-tiles), all 32 rows.
// B fragments (global) are prefetched one kk ahead; MMAs are ordered
// split-stage-outer so the 8 accumulators sit between same-acc reuses.
// ---------------------------------------------------------------------------
__device__ __forceinline__ void gemm_layer(
    const uint2* __restrict__ A, int aKKS, int kSteps,
    const uint2* __restrict__ WB, const float* __restrict__ bias,
    uint2* __restrict__ O, int oKKS, int tid)
{
    const int wn   = tid >> 5;
    const int lane = tid & 31;
    const int t    = lane & 3;

    float c[2][4][4];
#pragma unroll
    for (int m = 0; m < 2; m++)
#pragma unroll
        for (int nt = 0; nt < 4; nt++)
#pragma unroll
            for (int i = 0; i < 4; i++) c[m][nt][i] = 0.f;

    const uint2* a0p = A + lane;                  // mt = 0
    const uint2* a1p = A + aKKS * 128 + lane;     // mt = 1
    const uint2* wp  = WB + (wn * 4) * 64 + lane;

    unsigned bh[4][2], bl[4][2];
#pragma unroll
    for (int nt = 0; nt < 4; nt++) {
        uint2 w0 = wp[nt * 64];
        uint2 w1 = wp[nt * 64 + 32];
        bh[nt][0] = w0.x; bl[nt][0] = w0.y;
        bh[nt][1] = w1.x; bl[nt][1] = w1.y;
    }

#pragma unroll 2
    for (int kk = 0; kk < kSteps; kk++) {
        unsigned ah[2][4], al[2][4];
#pragma unroll
        for (int s = 0; s < 4; s++) {
            uint2 w0 = a0p[kk * 128 + s * 32];
            uint2 w1 = a1p[kk * 128 + s * 32];
            ah[0][s] = w0.x; al[0][s] = w0.y;
            ah[1][s] = w1.x; al[1][s] = w1.y;
        }

        // prefetch next kk's B fragments (clamped at the tail)
        unsigned nbh[4][2], nbl[4][2];
        {
            int nk = (kk + 1 < kSteps) ? kk + 1 : kk;
            const uint2* wk = wp + nk * 2048;
#pragma unroll
            for (int nt = 0; nt < 4; nt++) {
                uint2 w0 = wk[nt * 64];
                uint2 w1 = wk[nt * 64 + 32];
                nbh[nt][0] = w0.x; nbl[nt][0] = w0.y;
                nbh[nt][1] = w1.x; nbl[nt][1] = w1.y;
            }
        }

        // stage 1: hi*hi   (8 independent accumulators)
#pragma unroll
        for (int m = 0; m < 2; m++)
#pragma unroll
            for (int nt = 0; nt < 4; nt++)
                mma16816(c[m][nt], ah[m], bh[nt][0], bh[nt][1]);
        // stage 2: hi*lo
#pragma unroll
        for (int m = 0; m < 2; m++)
#pragma unroll
            for (int nt = 0; nt < 4; nt++)
                mma16816(c[m][nt], ah[m], bl[nt][0], bl[nt][1]);
        // stage 3: lo*hi
#pragma unroll
        for (int m = 0; m < 2; m++)
#pragma unroll
            for (int nt = 0; nt < 4; nt++)
                mma16816(c[m][nt], al[m], bh[nt][0], bh[nt][1]);

        // rotate prefetched B into place
#pragma unroll
        for (int nt = 0; nt < 4; nt++) {
            bh[nt][0] = nbh[nt][0]; bh[nt][1] = nbh[nt][1];
            bl[nt][0] = nbl[nt][0]; bl[nt][1] = nbl[nt][1];
        }
    }

    // Epilogue: bias + relu + split -> next layer's A-fragment layout.
    // (c0,c1) -> row g, (c2,c3) -> row g+8; kko = wn*2 + (nt>>1),
    // slot = (nt&1)*2 (+1 for row+8); lane unchanged.
#pragma unroll
    for (int m = 0; m < 2; m++)
#pragma unroll
        for (int nt = 0; nt < 4; nt++) {
            int col = wn * 32 + nt * 8 + 2 * t;
            float2 bv = *(const float2*)(bias + col);
            float v0 = fmaxf(c[m][nt][0] + bv.x, 0.f);
            float v1 = fmaxf(c[m][nt][1] + bv.y, 0.f);
            float v2 = fmaxf(c[m][nt][2] + bv.x, 0.f);
            float v3 = fmaxf(c[m][nt][3] + bv.y, 0.f);
            int kko  = wn * 2 + (nt >> 1);
            int slot = (nt & 1) * 2;
            O[((m * oKKS + kko) * 4 + slot    ) * 32 + lane] = split2(v0, v1);
            O[((m * oKKS + kko) * 4 + slot + 1) * 32 + lane] = split2(v2, v3);
        }
}

__global__ void __launch_bounds__(NTHREADS, 2)
topdown_kernel(const float* __restrict__ towers,
               const float* __restrict__ aggregate,
               const float* __restrict__ M1b,
               const float* __restrict__ M2b,
               const float* __restrict__ M3b,
               const float* __restrict__ O1b,
               const float* __restrict__ O2b,
               const float* __restrict__ O3w, const float* __restrict__ O3b,
               float* __restrict__ out)
{
    extern __shared__ uint2 smem2[];
    uint2* X  = smem2;            // XWORDS
    uint2* H1 = X + XWORDS;       // HWORDS
    uint2* H2 = H1 + HWORDS;      // HWORDS
    float* P  = (float*)(H2 + HWORDS);

    const int tid = threadIdx.x;
    const size_t row0 = (size_t)blockIdx.x * TM;

    // tower-word decomposition for this thread (1 word per thread per step)
    const int tw_mt   = tid >> 7;
    const int tw_rem  = tid & 127;
    const int tw_slot = tw_rem >> 5;
    const int tw_lane = tw_rem & 31;
    const int tw_r    = tw_mt * 16 + (tw_lane >> 2) + (tw_slot & 1) * 8;
    const int tw_koff = (tw_slot >> 1) * 8 + 2 * (tw_lane & 3);
    const float* tw_base = towers + (row0 + tw_r) * (size_t)(KTOT * NIN);
    const int tw_idx = ((tw_mt * KKX + 16) * 4 + tw_slot) * 32 + tw_lane;

    // init: summary region of X (kk 0..15) from aggregate, tower(0), P = 1
    for (int w = tid; w < 2 * KKH * 4 * 32; w += NTHREADS) {
        int mt   = w >> 11;
        int rem  = w & 2047;
        int kk   = rem >> 7;
        int rem2 = rem & 127;
        int slot = rem2 >> 5;
        int lane = rem2 & 31;
        int kp   = kk * 8 + (slot >> 1) * 4 + (lane & 3);
        X[((mt * KKX + kk) * 4 + slot) * 32 + lane] =
            split2(aggregate[2 * kp], aggregate[2 * kp + 1]);
    }
    {
        const float* tp = tw_base + (size_t)(KTOT - 1) * NIN;
        float v0 = (tw_koff     < NIN) ? tp[tw_koff]     : 0.f;
        float v1 = (tw_koff + 1 < NIN) ? tp[tw_koff + 1] : 0.f;
        X[tw_idx] = split2(v0, v1);
    }
    if (tid < TM) P[tid] = 1.f;
    __syncthreads();

    for (int s = 0; s < KTOT; s++) {
        // prefetch next step's tower values into registers (used in phase 5)
        float tv0 = 0.f, tv1 = 0.f;
        if (s + 1 < KTOT) {
            const float* tp = tw_base + (size_t)(KTOT - 2 - s) * NIN;
            if (tw_koff     < NIN) tv0 = tp[tw_koff];
            if (tw_koff + 1 < NIN) tv1 = tp[tw_koff + 1];
        }

        // phase 1: O1
        gemm_layer(X,  KKX, KKX, g_O1, O1b, H1, KKH, tid);
        __syncthreads();
        // phase 2: O2
        gemm_layer(H1, KKH, KKH, g_O2, O2b, H2, KKH, tid);
        __syncthreads();

        // phase 3: O3 (reads H2, writes P) + M1 (reads X, writes H1)
        {
            int r = tid >> 3, q = tid & 7;     // 8 threads per row, 16 kp each
            int mt = r >> 4;
            int rloc = r & 15;
            int g = rloc & 7;
            int rowhi = rloc >> 3;
            float sum = 0.f;
#pragma unroll 4
            for (int kp = q * 16; kp < q * 16 + 16; kp++) {
                int kk   = kp >> 3;
                int slot = ((kp >> 2) & 1) * 2 + rowhi;
                int lane = g * 4 + (kp & 3);
                uint2 wv = H2[((mt * KKH + kk) * 4 + slot) * 32 + lane];
                float v0 = bf_lo(wv.x) + bf_lo(wv.y);
                float v1 = bf_hi(wv.x) + bf_hi(wv.y);
                float2 ww = *(const float2*)(O3w + 2 * kp);
                sum = fmaf(v0, ww.x, fmaf(v1, ww.y, sum));
            }
            sum += __shfl_xor_sync(0xffffffffu, sum, 1);
            sum += __shfl_xor_sync(0xffffffffu, sum, 2);
            sum += __shfl_xor_sync(0xffffffffu, sum, 4);
            if (q == 0) {
                float logit = sum + O3b[0];
                P[r] *= 1.f / (1.f + expf(-logit));
            }
        }
        gemm_layer(X,  KKX, KKX, g_M1, M1b, H1, KKH, tid);
        __syncthreads();   // fences O3's H2 reads before M2 writes H2

        // phase 4: M2
        gemm_layer(H1, KKH, KKH, g_M2, M2b, H2, KKH, tid);
        __syncthreads();

        // phase 5: M3 (H2 -> X kk 0..15) + tower fill for s+1 (X kk 16)
        gemm_layer(H2, KKH, KKH, g_M3, M3b, X, KKX, tid);
        if (s + 1 < KTOT)
            X[tw_idx] = split2(tv0, tv1);
        __syncthreads();
    }

    if (tid < TM) out[row0 + tid] = P[tid];
}

extern "C" void kernel_launch(void* const* d_in, const int* in_sizes, int n_in,
                              void* d_out, int out_size)
{
    const float* towers    = (const float*)d_in[0];
    const float* aggregate = (const float*)d_in[1];
    const float* M1w = (const float*)d_in[2];
    const float* M1b = (const float*)d_in[3];
    const float* M2w = (const float*)d_in[4];
    const float* M2b = (const float*)d_in[5];
    const float* M3w = (const float*)d_in[6];
    const float* M3b = (const float*)d_in[7];
    const float* O1w = (const float*)d_in[8];
    const float* O1b = (const float*)d_in[9];
    const float* O2w = (const float*)d_in[10];
    const float* O2b = (const float*)d_in[11];
    const float* O3w = (const float*)d_in[12];
    const float* O3b = (const float*)d_in[13];
    float* out = (float*)d_out;

    const int N = in_sizes[0] / (KTOT * NIN);   // 131072

    prep_weights<<<(KKX * 2048 + 255) / 256, 256>>>(M1w, O1w, M2w, M3w, O2w);

    const size_t smem_bytes =
        (size_t)(XWORDS + 2 * HWORDS) * sizeof(uint2) + TM * sizeof(float);
    cudaFuncSetAttribute(topdown_kernel,
                         cudaFuncAttributeMaxDynamicSharedMemorySize,
                         (int)smem_bytes);

    topdown_kernel<<<N / TM, NTHREADS, smem_bytes>>>(
        towers, aggregate,
        M1b, M2b, M3b,
        O1b, O2b,
        O3w, O3b,
        out);
}

// round 16
// speedup vs baseline: 4.3212x; 1.0005x over previous
#include <cuda_runtime.h>
#include <cuda_bf16.h>
#include <math.h>

#define NIN 14
#define NH 256
#define KTOT 10
#define TM 32
#define NTHREADS 256
#define KKX 17              // k-steps for 272-wide input (256 summary + 14 tower + 2 pad)
#define KKH 16              // k-steps for 256-wide hidden
#define XWORDS (2 * KKX * 4 * 32)   // 4352 uint2 (TM/16 = 2 m-tiles)
#define HWORDS (2 * KKH * 4 * 32)   // 4096 uint2

// ---------------------------------------------------------------------------
// Fast split: value = hi(bf16) + lo(bf16), identical results to the RN/RN
// two-step split (hi = RN(v); lo = RN(v - hi)), but 6 ops per pair via
// cvt.rn.bf16x2.f32. Word packs a k-pair: low 16 = even-k, high 16 = odd-k.
// uint2: .x = hi-pair word, .y = lo-pair word.
// ---------------------------------------------------------------------------
__device__ __forceinline__ uint2 split2(float v0, float v1) {
    uint2 w;
    asm("cvt.rn.bf16x2.f32 %0, %1, %2;" : "=r"(w.x) : "f"(v1), "f"(v0));
    float h0 = __uint_as_float(w.x << 16);
    float h1 = __uint_as_float(w.x & 0xffff0000u);
    float r0 = v0 - h0;                 // exact (Sterbenz)
    float r1 = v1 - h1;
    asm("cvt.rn.bf16x2.f32 %0, %1, %2;" : "=r"(w.y) : "f"(r1), "f"(r0));
    return w;
}
__device__ __forceinline__ float bf_lo(unsigned w) {
    return __uint_as_float(w << 16);
}
__device__ __forceinline__ float bf_hi(unsigned w) {
    return __uint_as_float(w & 0xffff0000u);
}

// ---------------------------------------------------------------------------
// Fragment-major weight arrays (built once).
// Index: ((kk*32 + ntg)*2 + slot)*32 + lane
//   cols = ntg*8 + (lane>>2), k0 = kk*16 + slot*8 + 2*(lane&3)
//   word = { W[k0][col], W[k0+1][col] }  (hi pair in .x, lo pair in .y)
// ---------------------------------------------------------------------------
__device__ __align__(16) uint2 g_M1[KKX * 2048];
__device__ __align__(16) uint2 g_O1[KKX * 2048];
__device__ __align__(16) uint2 g_M2[KKH * 2048];
__device__ __align__(16) uint2 g_M3[KKH * 2048];
__device__ __align__(16) uint2 g_O2[KKH * 2048];

__global__ void prep_weights(const float* __restrict__ M1w,
                             const float* __restrict__ O1w,
                             const float* __restrict__ M2w,
                             const float* __restrict__ M3w,
                             const float* __restrict__ O2w) {
    int w = blockIdx.x * blockDim.x + threadIdx.x;
    if (w >= KKX * 2048) return;
    int kk   = w >> 11;
    int rem  = w & 2047;
    int ntg  = rem >> 6;
    int slot = (rem >> 5) & 1;
    int lane = rem & 31;
    int k0   = kk * 16 + slot * 8 + 2 * (lane & 3);
    int col  = ntg * 8 + (lane >> 2);

    float a0 = (k0     < 270) ? M1w[k0 * NH + col]       : 0.f;
    float a1 = (k0 + 1 < 270) ? M1w[(k0 + 1) * NH + col] : 0.f;
    g_M1[w] = split2(a0, a1);
    a0 = (k0     < 270) ? O1w[k0 * NH + col]       : 0.f;
    a1 = (k0 + 1 < 270) ? O1w[(k0 + 1) * NH + col] : 0.f;
    g_O1[w] = split2(a0, a1);

    if (kk < KKH) {
        g_M2[w] = split2(M2w[k0 * NH + col], M2w[(k0 + 1) * NH + col]);
        g_M3[w] = split2(M3w[k0 * NH + col], M3w[(k0 + 1) * NH + col]);
        g_O2[w] = split2(O2w[k0 * NH + col], O2w[(k0 + 1) * NH + col]);
    }
}

__device__ __forceinline__ void mma16816(float c[4], const unsigned a[4],
                                         unsigned b0, unsigned b1) {
    asm("mma.sync.aligned.m16n8k16.row.col.f32.bf16.bf16.f32 "
        "{%0,%1,%2,%3}, {%4,%5,%6,%7}, {%8,%9}, {%0,%1,%2,%3};"
        : "+f"(c[0]), "+f"(c[1]), "+f"(c[2]), "+f"(c[3])
        : "r"(a[0]), "r"(a[1]), "r"(a[2]), "r"(a[3]), "r"(b0), "r"(b1));
}

// ---------------------------------------------------------------------------
// One layer: O[32][256] = relu(A[32][16*kSteps] @ W + bias), split-bf16 3-MMA.
// Activation buffers, fragment-major uint2:
//   idx(mt, kk, slot, lane) = ((mt*KKS + kk)*4 + slot)*32 + lane
//   rows r = mt*16 + (lane>>2) + (slot&1)*8,
//   k-pair kp = kk*8 + (slot>>1)*4 + (lane&3) -> A[r,2kp], A[r,2kp+1]
// 8 warps; warp wn covers cols wn*32..+31 (4 n-tiles), all 32 rows.
// B fragments (global) are prefetched one kk ahead; MMAs are ordered
// split-stage-outer so the 8 accumulators sit between same-acc reuses.
// ---------------------------------------------------------------------------
__device__ __forceinline__ void gemm_layer(
    const uint2* __restrict__ A, int aKKS, int kSteps,
    const uint2* __restrict__ WB, const float* __restrict__ bias,
    uint2* __restrict__ O, int oKKS, int tid)
{
    const int wn   = tid >> 5;
    const int lane = tid & 31;
    const int t    = lane & 3;

    float c[2][4][4];
#pragma unroll
    for (int m = 0; m < 2; m++)
#pragma unroll
        for (int nt = 0; nt < 4; nt++)
#pragma unroll
            for (int i = 0; i < 4; i++) c[m][nt][i] = 0.f;

    const uint2* a0p = A + lane;                  // mt = 0
    const uint2* a1p = A + aKKS * 128 + lane;     // mt = 1
    const uint2* wp  = WB + (wn * 4) * 64 + lane;

    unsigned bh[4][2], bl[4][2];
#pragma unroll
    for (int nt = 0; nt < 4; nt++) {
        uint2 w0 = wp[nt * 64];
        uint2 w1 = wp[nt * 64 + 32];
        bh[nt][0] = w0.x; bl[nt][0] = w0.y;
        bh[nt][1] = w1.x; bl[nt][1] = w1.y;
    }

#pragma unroll 2
    for (int kk = 0; kk < kSteps; kk++) {
        unsigned ah[2][4], al[2][4];
#pragma unroll
        for (int s = 0; s < 4; s++) {
            uint2 w0 = a0p[kk * 128 + s * 32];
            uint2 w1 = a1p[kk * 128 + s * 32];
            ah[0][s] = w0.x; al[0][s] = w0.y;
            ah[1][s] = w1.x; al[1][s] = w1.y;
        }

        // prefetch next kk's B fragments (clamped at the tail)
        unsigned nbh[4][2], nbl[4][2];
        {
            int nk = (kk + 1 < kSteps) ? kk + 1 : kk;
            const uint2* wk = wp + nk * 2048;
#pragma unroll
            for (int nt = 0; nt < 4; nt++) {
                uint2 w0 = wk[nt * 64];
                uint2 w1 = wk[nt * 64 + 32];
                nbh[nt][0] = w0.x; nbl[nt][0] = w0.y;
                nbh[nt][1] = w1.x; nbl[nt][1] = w1.y;
            }
        }

        // stage 1: hi*hi   (8 independent accumulators)
#pragma unroll
        for (int m = 0; m < 2; m++)
#pragma unroll
            for (int nt = 0; nt < 4; nt++)
                mma16816(c[m][nt], ah[m], bh[nt][0], bh[nt][1]);
        // stage 2: hi*lo
#pragma unroll
        for (int m = 0; m < 2; m++)
#pragma unroll
            for (int nt = 0; nt < 4; nt++)
                mma16816(c[m][nt], ah[m], bl[nt][0], bl[nt][1]);
        // stage 3: lo*hi
#pragma unroll
        for (int m = 0; m < 2; m++)
#pragma unroll
            for (int nt = 0; nt < 4; nt++)
                mma16816(c[m][nt], al[m], bh[nt][0], bh[nt][1]);

        // rotate prefetched B into place
#pragma unroll
        for (int nt = 0; nt < 4; nt++) {
            bh[nt][0] = nbh[nt][0]; bh[nt][1] = nbh[nt][1];
            bl[nt][0] = nbl[nt][0]; bl[nt][1] = nbl[nt][1];
        }
    }

    // Epilogue: bias + relu + split -> next layer's A-fragment layout.
    // (c0,c1) -> row g, (c2,c3) -> row g+8; kko = wn*2 + (nt>>1),
    // slot = (nt&1)*2 (+1 for row+8); lane unchanged.
#pragma unroll
    for (int m = 0; m < 2; m++)
#pragma unroll
        for (int nt = 0; nt < 4; nt++) {
            int col = wn * 32 + nt * 8 + 2 * t;
            float2 bv = *(const float2*)(bias + col);
            float v0 = fmaxf(c[m][nt][0] + bv.x, 0.f);
            float v1 = fmaxf(c[m][nt][1] + bv.y, 0.f);
            float v2 = fmaxf(c[m][nt][2] + bv.x, 0.f);
            float v3 = fmaxf(c[m][nt][3] + bv.y, 0.f);
            int kko  = wn * 2 + (nt >> 1);
            int slot = (nt & 1) * 2;
            O[((m * oKKS + kko) * 4 + slot    ) * 32 + lane] = split2(v0, v1);
            O[((m * oKKS + kko) * 4 + slot + 1) * 32 + lane] = split2(v2, v3);
        }
}

__global__ void __launch_bounds__(NTHREADS, 2)
topdown_kernel(const float* __restrict__ towers,
               const float* __restrict__ aggregate,
               const float* __restrict__ M1b,
               const float* __restrict__ M2b,
               const float* __restrict__ M3b,
               const float* __restrict__ O1b,
               const float* __restrict__ O2b,
               const float* __restrict__ O3w, const float* __restrict__ O3b,
               float* __restrict__ out)
{
    extern __shared__ uint2 smem2[];
    uint2* X  = smem2;            // XWORDS
    uint2* H1 = X + XWORDS;       // HWORDS
    uint2* H2 = H1 + HWORDS;      // HWORDS
    float* P  = (float*)(H2 + HWORDS);

    const int tid = threadIdx.x;
    const size_t row0 = (size_t)blockIdx.x * TM;

    // tower-word decomposition for this thread (1 word per thread per step)
    const int tw_mt   = tid >> 7;
    const int tw_rem  = tid & 127;
    const int tw_slot = tw_rem >> 5;
    const int tw_lane = tw_rem & 31;
    const int tw_r    = tw_mt * 16 + (tw_lane >> 2) + (tw_slot & 1) * 8;
    const int tw_koff = (tw_slot >> 1) * 8 + 2 * (tw_lane & 3);
    const float* tw_base = towers + (row0 + tw_r) * (size_t)(KTOT * NIN);
    const int tw_idx = ((tw_mt * KKX + 16) * 4 + tw_slot) * 32 + tw_lane;

    // init: summary region of X (kk 0..15) from aggregate, tower(0), P = 1
    for (int w = tid; w < 2 * KKH * 4 * 32; w += NTHREADS) {
        int mt   = w >> 11;
        int rem  = w & 2047;
        int kk   = rem >> 7;
        int rem2 = rem & 127;
        int slot = rem2 >> 5;
        int lane = rem2 & 31;
        int kp   = kk * 8 + (slot >> 1) * 4 + (lane & 3);
        X[((mt * KKX + kk) * 4 + slot) * 32 + lane] =
            split2(aggregate[2 * kp], aggregate[2 * kp + 1]);
    }
    {
        const float* tp = tw_base + (size_t)(KTOT - 1) * NIN;
        float v0 = (tw_koff     < NIN) ? tp[tw_koff]     : 0.f;
        float v1 = (tw_koff + 1 < NIN) ? tp[tw_koff + 1] : 0.f;
        X[tw_idx] = split2(v0, v1);
    }
    if (tid < TM) P[tid] = 1.f;
    __syncthreads();

    for (int s = 0; s < KTOT; s++) {
        // prefetch next step's tower values into registers (used in phase 5)
        float tv0 = 0.f, tv1 = 0.f;
        if (s + 1 < KTOT) {
            const float* tp = tw_base + (size_t)(KTOT - 2 - s) * NIN;
            if (tw_koff     < NIN) tv0 = tp[tw_koff];
            if (tw_koff + 1 < NIN) tv1 = tp[tw_koff + 1];
        }

        // phase 1: O1
        gemm_layer(X,  KKX, KKX, g_O1, O1b, H1, KKH, tid);
        __syncthreads();
        // phase 2: O2
        gemm_layer(H1, KKH, KKH, g_O2, O2b, H2, KKH, tid);
        __syncthreads();

        // phase 3: O3 (reads H2, writes P) + M1 (reads X, writes H1)
        {
            int r = tid >> 3, q = tid & 7;     // 8 threads per row, 16 kp each
            int mt = r >> 4;
            int rloc = r & 15;
            int g = rloc & 7;
            int rowhi = rloc >> 3;
            float sum = 0.f;
#pragma unroll 4
            for (int kp = q * 16; kp < q * 16 + 16; kp++) {
                int kk   = kp >> 3;
                int slot = ((kp >> 2) & 1) * 2 + rowhi;
                int lane = g * 4 + (kp & 3);
                uint2 wv = H2[((mt * KKH + kk) * 4 + slot) * 32 + lane];
                float v0 = bf_lo(wv.x) + bf_lo(wv.y);
                float v1 = bf_hi(wv.x) + bf_hi(wv.y);
                float2 ww = *(const float2*)(O3w + 2 * kp);
                sum = fmaf(v0, ww.x, fmaf(v1, ww.y, sum));
            }
            sum += __shfl_xor_sync(0xffffffffu, sum, 1);
            sum += __shfl_xor_sync(0xffffffffu, sum, 2);
            sum += __shfl_xor_sync(0xffffffffu, sum, 4);
            if (q == 0) {
                float logit = sum + O3b[0];
                P[r] *= 1.f / (1.f + expf(-logit));
            }
        }
        gemm_layer(X,  KKX, KKX, g_M1, M1b, H1, KKH, tid);
        __syncthreads();   // fences O3's H2 reads before M2 writes H2

        // phase 4: M2
        gemm_layer(H1, KKH, KKH, g_M2, M2b, H2, KKH, tid);
        __syncthreads();

        // phase 5: M3 (H2 -> X kk 0..15) + tower fill for s+1 (X kk 16)
        gemm_layer(H2, KKH, KKH, g_M3, M3b, X, KKX, tid);
        if (s + 1 < KTOT)
            X[tw_idx] = split2(tv0, tv1);
        __syncthreads();
    }

    if (tid < TM) out[row0 + tid] = P[tid];
}

extern "C" void kernel_launch(void* const* d_in, const int* in_sizes, int n_in,
                              void* d_out, int out_size)
{
    const float* towers    = (const float*)d_in[0];
    const float* aggregate = (const float*)d_in[1];
    const float* M1w = (const float*)d_in[2];
    const float* M1b = (const float*)d_in[3];
    const float* M2w = (const float*)d_in[4];
    const float* M2b = (const float*)d_in[5];
    const float* M3w = (const float*)d_in[6];
    const float* M3b = (const float*)d_in[7];
    const float* O1w = (const float*)d_in[8];
    const float* O1b = (const float*)d_in[9];
    const float* O2w = (const float*)d_in[10];
    const float* O2b = (const float*)d_in[11];
    const float* O3w = (const float*)d_in[12];
    const float* O3b = (const float*)d_in[13];
    float* out = (float*)d_out;

    const int N = in_sizes[0] / (KTOT * NIN);   // 131072

    prep_weights<<<(KKX * 2048 + 255) / 256, 256>>>(M1w, O1w, M2w, M3w, O2w);

    const size_t smem_bytes =
        (size_t)(XWORDS + 2 * HWORDS) * sizeof(uint2) + TM * sizeof(float);
    cudaFuncSetAttribute(topdown_kernel,
                         cudaFuncAttributeMaxDynamicSharedMemorySize,
                         (int)smem_bytes);

    topdown_kernel<<<N / TM, NTHREADS, smem_bytes>>>(
        towers, aggregate,
        M1b, M2b, M3b,
        O1b, O2b,
        O3w, O3b,
        out);
}